// round 2
// baseline (speedup 1.0000x reference)
#include <cuda_runtime.h>

// Problem constants (shapes fixed by the dataset): B=8192, S=4096.
#define MAX_B 8192
#define THREADS 256

__device__ float g_partial[MAX_B];

// One CTA per row. 256 threads, each handles S/256 = 16 elements via 4x float4/int4.
__global__ void __launch_bounds__(THREADS)
focal_row_kernel(const float* __restrict__ scores,
                 const int* __restrict__ head,
                 const int* __restrict__ tail,
                 const int* __restrict__ mask,
                 int S)
{
    const int b   = blockIdx.x;
    const int tid = threadIdx.x;

    const float* __restrict__ srow = scores + (size_t)b * S;
    const int*   __restrict__ mrow = mask   + (size_t)b * S;

    const int hp = head[b];
    const int tp = tail[b];
    const float pos = __ldg(srow + tp);

    float sum = 0.0f;
    int   cnt = 0;

    const int n4 = S >> 2;                 // float4 count per row (1024)
    const int iters = n4 / THREADS;        // 4

    #pragma unroll
    for (int it = 0; it < iters; ++it) {
        const int c4 = it * THREADS + tid;
        const float4 sv = reinterpret_cast<const float4*>(srow)[c4];
        const int4   mv = reinterpret_cast<const int4*>(mrow)[c4];
        const int col = c4 << 2;

        const float sarr[4] = { sv.x, sv.y, sv.z, sv.w };
        const int   marr[4] = { mv.x, mv.y, mv.z, mv.w };

        #pragma unroll
        for (int j = 0; j < 4; ++j) {
            const int c = col + j;
            const bool ok = (marr[j] == 1) && (c != hp) && (c != tp);
            // d = score - pos
            const float d  = sarr[j] - pos;
            const float ad = fabsf(d);
            const float e  = __expf(-ad);            // exp(-|d|) in (0,1]
            // softplus(d) = max(d,0) + log(1+exp(-|d|)); 1+e in (1,2] -> __logf safe
            const float sp = fmaxf(d, 0.0f) + __logf(1.0f + e);
            // pt = sigmoid(-d) = exp(-softplus(d)), computed exactly:
            //   d>0:  e/(1+e)   d<=0:  1/(1+e)
            const float inv = __frcp_rn(1.0f + e);
            float pt = (d > 0.0f ? e : 1.0f) * inv;
            pt = fminf(fmaxf(pt, 1e-7f), 1.0f - 1e-7f);
            const float om = 1.0f - pt;
            // fl = -ALPHA*(1-pt)^GAMMA*logpt = (1-pt)^2 * softplus(d)
            const float fl = om * om * sp;
            if (ok) { sum += fl; cnt += 1; }
        }
    }

    // Deterministic block reduction: warp shuffles + shared across 8 warps.
    #pragma unroll
    for (int o = 16; o > 0; o >>= 1) {
        sum += __shfl_down_sync(0xffffffffu, sum, o);
        cnt += __shfl_down_sync(0xffffffffu, cnt, o);
    }
    __shared__ float ssum[8];
    __shared__ int   scnt[8];
    const int wid = tid >> 5, lid = tid & 31;
    if (lid == 0) { ssum[wid] = sum; scnt[wid] = cnt; }
    __syncthreads();
    if (wid == 0) {
        sum = (lid < 8) ? ssum[lid] : 0.0f;
        cnt = (lid < 8) ? scnt[lid] : 0;
        #pragma unroll
        for (int o = 4; o > 0; o >>= 1) {
            sum += __shfl_down_sync(0xffffffffu, sum, o);
            cnt += __shfl_down_sync(0xffffffffu, cnt, o);
        }
        if (lid == 0)
            g_partial[b] = (cnt > 0) ? sum / (float)cnt : 0.0f;
    }
}

// Single-CTA deterministic final reduction over B per-row values.
__global__ void __launch_bounds__(1024)
focal_final_kernel(float* __restrict__ out, int B)
{
    const int tid = threadIdx.x;
    float sum = 0.0f;
    for (int i = tid; i < B; i += 1024) sum += g_partial[i];

    #pragma unroll
    for (int o = 16; o > 0; o >>= 1)
        sum += __shfl_down_sync(0xffffffffu, sum, o);

    __shared__ float ssum[32];
    const int wid = tid >> 5, lid = tid & 31;
    if (lid == 0) ssum[wid] = sum;
    __syncthreads();
    if (wid == 0) {
        sum = (lid < 32) ? ssum[lid] : 0.0f;
        #pragma unroll
        for (int o = 16; o > 0; o >>= 1)
            sum += __shfl_down_sync(0xffffffffu, sum, o);
        if (lid == 0) out[0] = sum / (float)B;
    }
}

extern "C" void kernel_launch(void* const* d_in, const int* in_sizes, int n_in,
                              void* d_out, int out_size)
{
    // metadata order: scores [B,S] f32, head [B] i32, tail [B] i32, mask [B,S] i32
    const float* scores = (const float*)d_in[0];
    const int*   head   = (const int*)d_in[1];
    const int*   tail   = (const int*)d_in[2];
    const int*   mask   = (const int*)d_in[3];
    float* out = (float*)d_out;

    const int B = in_sizes[1];
    const int S = in_sizes[0] / B;

    focal_row_kernel<<<B, THREADS>>>(scores, head, tail, mask, S);
    focal_final_kernel<<<1, 1024>>>(out, B);
}